// round 11
// baseline (speedup 1.0000x reference)
#include <cuda_runtime.h>
#include <cuda_bf16.h>
#include <cuda_fp16.h>
#include <cstdint>
#include <math.h>

#define B_    2
#define L_    2048
#define DIM_  1024
#define H_    16
#define DH_   64
#define N3_   3072
#define SCALE_ 0.125f

// ---------------- device scratch ----------------
__device__ __nv_bfloat16 g_ahi[B_ * L_ * DIM_];      // x-split, later z-split
__device__ __nv_bfloat16 g_alo[B_ * L_ * DIM_];
__device__ __nv_bfloat16 g_wqt_hi[N3_ * DIM_];
__device__ __nv_bfloat16 g_wqt_lo[N3_ * DIM_];
__device__ __nv_bfloat16 g_wot_hi[DIM_ * DIM_];
__device__ __nv_bfloat16 g_wot_lo[DIM_ * DIM_];
// attention operands [b,h,l,64] (written by QKV GEMM epilogue)
__device__ __nv_bfloat16 g_qh[B_ * H_ * L_ * DH_];   // scaled by 0.125
__device__ __nv_bfloat16 g_ql[B_ * H_ * L_ * DH_];
__device__ __nv_bfloat16 g_kh[B_ * H_ * L_ * DH_];
__device__ __nv_bfloat16 g_kl[B_ * H_ * L_ * DH_];
__device__ __half        g_vf[B_ * H_ * L_ * DH_];   // V single fp16
__device__ __nv_bfloat16 g_maskb[B_ * L_ * L_];

// ---------------- helpers ----------------
__device__ __forceinline__ uint32_t smem_u32(const void* p) {
    uint32_t a;
    asm("{ .reg .u64 t; cvta.to.shared.u64 t, %1; cvt.u32.u64 %0, t; }" : "=r"(a) : "l"(p));
    return a;
}
__device__ __forceinline__ void cpasync16(uint32_t s, const void* g) {
    asm volatile("cp.async.cg.shared.global [%0], [%1], 16;" :: "r"(s), "l"(g));
}
#define CP_COMMIT() asm volatile("cp.async.commit_group;")
#define CP_WAIT(n)  asm volatile("cp.async.wait_group %0;" :: "n"(n))

__device__ __forceinline__ void ldsm_x4(uint32_t r[4], uint32_t addr) {
    asm volatile("ldmatrix.sync.aligned.m8n8.x4.shared.b16 {%0,%1,%2,%3}, [%4];"
                 : "=r"(r[0]), "=r"(r[1]), "=r"(r[2]), "=r"(r[3]) : "r"(addr));
}
__device__ __forceinline__ void ldsm_x4_t(uint32_t r[4], uint32_t addr) {
    asm volatile("ldmatrix.sync.aligned.m8n8.x4.trans.shared.b16 {%0,%1,%2,%3}, [%4];"
                 : "=r"(r[0]), "=r"(r[1]), "=r"(r[2]), "=r"(r[3]) : "r"(addr));
}
__device__ __forceinline__ void mma_bf16(float c[4], const uint32_t a[4], const uint32_t b[2]) {
    asm volatile(
        "mma.sync.aligned.m16n8k16.row.col.f32.bf16.bf16.f32 "
        "{%0,%1,%2,%3}, {%4,%5,%6,%7}, {%8,%9}, {%0,%1,%2,%3};"
        : "+f"(c[0]), "+f"(c[1]), "+f"(c[2]), "+f"(c[3])
        : "r"(a[0]), "r"(a[1]), "r"(a[2]), "r"(a[3]), "r"(b[0]), "r"(b[1]));
}
__device__ __forceinline__ void mma_f16(float c[4], const uint32_t a[4], const uint32_t b[2]) {
    asm volatile(
        "mma.sync.aligned.m16n8k16.row.col.f32.f16.f16.f32 "
        "{%0,%1,%2,%3}, {%4,%5,%6,%7}, {%8,%9}, {%0,%1,%2,%3};"
        : "+f"(c[0]), "+f"(c[1]), "+f"(c[2]), "+f"(c[3])
        : "r"(a[0]), "r"(a[1]), "r"(a[2]), "r"(a[3]), "r"(b[0]), "r"(b[1]));
}
__device__ __forceinline__ uint32_t bfpack(float lo, float hi) {
    uint32_t r;
    asm("cvt.rn.bf16x2.f32 %0, %1, %2;" : "=r"(r) : "f"(hi), "f"(lo));
    return r;
}
__device__ __forceinline__ uint32_t hpack(float lo, float hi) {
    uint32_t r;
    asm("cvt.rn.f16x2.f32 %0, %1, %2;" : "=r"(r) : "f"(hi), "f"(lo));
    return r;
}
__device__ __forceinline__ float bf_lo(uint32_t u) { return __uint_as_float(u << 16); }
__device__ __forceinline__ float bf_hi(uint32_t u) { return __uint_as_float(u & 0xffff0000u); }
__device__ __forceinline__ uint32_t lds32(uint32_t a) {
    uint32_t v;
    asm volatile("ld.shared.b32 %0, [%1];" : "=r"(v) : "r"(a));
    return v;
}

// ---------------------------------------------------------------------------
// fp32 -> (hi, lo) bf16 split
// ---------------------------------------------------------------------------
__global__ __launch_bounds__(256) void split_fp32(
    const float* __restrict__ in, __nv_bfloat16* __restrict__ hi,
    __nv_bfloat16* __restrict__ lo, int n4)
{
    int i = blockIdx.x * blockDim.x + threadIdx.x;
    if (i >= n4) return;
    float4 v = ((const float4*)in)[i];
    float vv[4] = {v.x, v.y, v.z, v.w};
    __nv_bfloat16 h[4], l[4];
#pragma unroll
    for (int k = 0; k < 4; k++) {
        h[k] = __float2bfloat16(vv[k]);
        l[k] = __float2bfloat16(vv[k] - __bfloat162float(h[k]));
    }
    ((uint2*)hi)[i] = *(uint2*)h;
    ((uint2*)lo)[i] = *(uint2*)l;
}

// fp32 mask -> bf16 (0/1 exact)
__global__ __launch_bounds__(256) void mask_bf16(
    const float* __restrict__ in, __nv_bfloat16* __restrict__ o, int n4)
{
    int i = blockIdx.x * blockDim.x + threadIdx.x;
    if (i >= n4) return;
    float4 v = ((const float4*)in)[i];
    __nv_bfloat16 h[4] = {__float2bfloat16(v.x), __float2bfloat16(v.y),
                          __float2bfloat16(v.z), __float2bfloat16(v.w)};
    ((uint2*)o)[i] = *(uint2*)h;
}

// ---------------------------------------------------------------------------
// fp32 [R,C] -> transposed split bf16 [C,R] (weights)
// ---------------------------------------------------------------------------
__global__ __launch_bounds__(256) void transpose_split(
    const float* __restrict__ in, __nv_bfloat16* __restrict__ ohi,
    __nv_bfloat16* __restrict__ olo, int R, int C)
{
    __shared__ float t[32][33];
    int cb = blockIdx.x * 32, rb = blockIdx.y * 32;
    int tx = threadIdx.x, ty = threadIdx.y;
#pragma unroll
    for (int i = 0; i < 4; i++)
        t[ty + 8 * i][tx] = in[(size_t)(rb + ty + 8 * i) * C + cb + tx];
    __syncthreads();
#pragma unroll
    for (int i = 0; i < 4; i++) {
        float v = t[tx][ty + 8 * i];
        __nv_bfloat16 h = __float2bfloat16(v);
        __nv_bfloat16 l = __float2bfloat16(v - __bfloat162float(h));
        size_t o = (size_t)(cb + ty + 8 * i) * R + rb + tx;
        ohi[o] = h;
        olo[o] = l;
    }
}

// ---------------------------------------------------------------------------
// HMMA bf16-split GEMM, 3-stage cp.async pipeline.
// QKVOUT=true: q/k split bf16, v fp16, [b,h,l,64] (q scaled by 2^-3, exact).
// QKVOUT=false: fp32 C + bias.
// launch_bounds (256,1): (256,2) caps regs at 128 -> spills (round-6).
// ---------------------------------------------------------------------------
#define MMPAD 40
#define STG_BYTES (4 * 128 * MMPAD * 2)   // 40960 per stage
#define OFF_AH 0
#define OFF_AL (128 * MMPAD * 2)
#define OFF_BH (2 * 128 * MMPAD * 2)
#define OFF_BL (3 * 128 * MMPAD * 2)
#define GEMM_SMEM (3 * STG_BYTES)         // 122880

template <bool QKVOUT>
__global__ __launch_bounds__(256, 1) void mm_hmma(
    const __nv_bfloat16* __restrict__ Ahi, const __nv_bfloat16* __restrict__ Alo,
    const __nv_bfloat16* __restrict__ Bhi, const __nv_bfloat16* __restrict__ Blo,
    const float* __restrict__ bias, float* __restrict__ C,
    __nv_bfloat16* __restrict__ qh, __nv_bfloat16* __restrict__ ql,
    __nv_bfloat16* __restrict__ kh, __nv_bfloat16* __restrict__ kl,
    __half* __restrict__ vf,
    int M, int N, int K)
{
    extern __shared__ char smem[];
    uint32_t sb = smem_u32(smem);
    int tid = threadIdx.x, wid = tid >> 5, lane = tid & 31;
    int m0 = blockIdx.y * 128, n0 = blockIdx.x * 128;
    int wm = wid & 3, wn = wid >> 2;

    const __nv_bfloat16* gAh = Ahi + (size_t)m0 * K;
    const __nv_bfloat16* gAl = Alo + (size_t)m0 * K;
    const __nv_bfloat16* gBh = Bhi + (size_t)n0 * K;
    const __nv_bfloat16* gBl = Blo + (size_t)n0 * K;

    int r0 = (tid + 0) >> 2, c80 = ((tid + 0) & 3) * 8;
    int r1 = (tid + 256) >> 2, c81 = ((tid + 256) & 3) * 8;

    auto load_chunk = [&](int c) {
        uint32_t stg = sb + (c % 3) * STG_BYTES;
        int kc = c * 32;
        size_t go0 = (size_t)r0 * K + kc + c80, go1 = (size_t)r1 * K + kc + c81;
        uint32_t so0 = (r0 * MMPAD + c80) * 2, so1 = (r1 * MMPAD + c81) * 2;
        cpasync16(stg + OFF_AH + so0, gAh + go0); cpasync16(stg + OFF_AH + so1, gAh + go1);
        cpasync16(stg + OFF_AL + so0, gAl + go0); cpasync16(stg + OFF_AL + so1, gAl + go1);
        cpasync16(stg + OFF_BH + so0, gBh + go0); cpasync16(stg + OFF_BH + so1, gBh + go1);
        cpasync16(stg + OFF_BL + so0, gBl + go0); cpasync16(stg + OFF_BL + so1, gBl + go1);
    };

    float acc[2][8][4];
#pragma unroll
    for (int mi = 0; mi < 2; mi++)
#pragma unroll
        for (int ni = 0; ni < 8; ni++)
#pragma unroll
            for (int j = 0; j < 4; j++) acc[mi][ni][j] = 0.0f;

    const int NCH = K >> 5;
    uint32_t a_row = wm * 32 + (lane & 15);
    uint32_t a_k8 = (lane >> 4) * 8;
    uint32_t b_row = wn * 64 + (lane & 7) + ((lane >> 4) << 3);
    uint32_t b_k8 = ((lane >> 3) & 1) * 8;

    // prologue: stages 0, 1
    load_chunk(0); CP_COMMIT();
    load_chunk(1); CP_COMMIT();

    for (int c = 0; c < NCH; c++) {
        if (c + 2 < NCH)      { load_chunk(c + 2); CP_COMMIT(); CP_WAIT(2); }
        else if (c + 1 < NCH) { CP_WAIT(1); }
        else                  { CP_WAIT(0); }
        __syncthreads();

        uint32_t stg = sb + (c % 3) * STG_BYTES;
#pragma unroll
        for (int ks = 0; ks < 2; ks++) {
            uint32_t ah[2][4], al[2][4];
#pragma unroll
            for (int mi = 0; mi < 2; mi++) {
                uint32_t ao = ((a_row + mi * 16) * MMPAD + ks * 16 + a_k8) * 2;
                ldsm_x4(ah[mi], stg + OFF_AH + ao);
                ldsm_x4(al[mi], stg + OFF_AL + ao);
            }
#pragma unroll
            for (int half = 0; half < 2; half++) {
                uint32_t bh[2][4], bl[2][4];
#pragma unroll
                for (int nb = 0; nb < 2; nb++) {
                    uint32_t bo = ((b_row + (half * 2 + nb) * 16) * MMPAD + ks * 16 + b_k8) * 2;
                    ldsm_x4(bh[nb], stg + OFF_BH + bo);
                    ldsm_x4(bl[nb], stg + OFF_BL + bo);
                }
#pragma unroll
                for (int mi = 0; mi < 2; mi++)
#pragma unroll
                    for (int nq = 0; nq < 4; nq++)
                        mma_bf16(acc[mi][half * 4 + nq], ah[mi], &bh[nq >> 1][(nq & 1) * 2]);
#pragma unroll
                for (int mi = 0; mi < 2; mi++)
#pragma unroll
                    for (int nq = 0; nq < 4; nq++)
                        mma_bf16(acc[mi][half * 4 + nq], al[mi], &bh[nq >> 1][(nq & 1) * 2]);
#pragma unroll
                for (int mi = 0; mi < 2; mi++)
#pragma unroll
                    for (int nq = 0; nq < 4; nq++)
                        mma_bf16(acc[mi][half * 4 + nq], ah[mi], &bl[nq >> 1][(nq & 1) * 2]);
            }
        }
        __syncthreads();
    }

    if (QKVOUT) {
        int gcol0 = n0 + wn * 64;
        int which = gcol0 >> 10;          // 0=q, 1=k, 2=v
        int hh = (gcol0 & 1023) >> 6;
        int rbase = m0 + wm * 32 + (lane >> 2);
        int d0 = (lane & 3) * 2;
        if (which == 2) {
            // V: single fp16
#pragma unroll
            for (int mi = 0; mi < 2; mi++) {
#pragma unroll
                for (int ni = 0; ni < 8; ni++) {
                    int d = d0 + ni * 8;
#pragma unroll
                    for (int half = 0; half < 2; half++) {
                        int rr = rbase + mi * 16 + half * 8;
                        int bb = rr >> 11, ll = rr & 2047;
                        uint32_t vp = hpack(acc[mi][ni][half * 2 + 0],
                                            acc[mi][ni][half * 2 + 1]);
                        size_t o = ((size_t)(bb * H_ + hh) * L_ + ll) * DH_ + d;
                        *(uint32_t*)(vf + o) = vp;
                    }
                }
            }
        } else {
            float scale = (which == 0) ? SCALE_ : 1.0f;
            __nv_bfloat16* dhi = (which == 0) ? qh : kh;
            __nv_bfloat16* dlo = (which == 0) ? ql : kl;
#pragma unroll
            for (int mi = 0; mi < 2; mi++) {
#pragma unroll
                for (int ni = 0; ni < 8; ni++) {
                    int d = d0 + ni * 8;
#pragma unroll
                    for (int half = 0; half < 2; half++) {
                        int rr = rbase + mi * 16 + half * 8;
                        int bb = rr >> 11, ll = rr & 2047;
                        float v0 = acc[mi][ni][half * 2 + 0] * scale;
                        float v1 = acc[mi][ni][half * 2 + 1] * scale;
                        uint32_t hp = bfpack(v0, v1);
                        uint32_t lp = bfpack(v0 - bf_lo(hp), v1 - bf_hi(hp));
                        size_t o = ((size_t)(bb * H_ + hh) * L_ + ll) * DH_ + d;
                        *(uint32_t*)(dhi + o) = hp;
                        *(uint32_t*)(dlo + o) = lp;
                    }
                }
            }
        }
    } else {
        int rbase = m0 + wm * 32 + (lane >> 2);
        int cb0 = n0 + wn * 64 + (lane & 3) * 2;
#pragma unroll
        for (int mi = 0; mi < 2; mi++) {
#pragma unroll
            for (int ni = 0; ni < 8; ni++) {
                int rr = rbase + mi * 16;
                int cc = cb0 + ni * 8;
                float b0 = bias[cc], b1 = bias[cc + 1];
                float2 v0 = {acc[mi][ni][0] + b0, acc[mi][ni][1] + b1};
                float2 v1 = {acc[mi][ni][2] + b0, acc[mi][ni][3] + b1};
                *(float2*)&C[(size_t)rr * N + cc] = v0;
                *(float2*)&C[(size_t)(rr + 8) * N + cc] = v1;
            }
        }
    }
}

// ---------------------------------------------------------------------------
// Tensor-core flash attention, post-softmax mask + renorm, 3-stage pipeline.
// Q tile 128 x KV block 64, 8 warps. S = QK^T 3-pass bf16 split;
// P,V in fp16 -> single-pass PV. No Zf track (EPS term ~2e-10).
// Stage layout (bytes): KH 9216 | KL 9216 | VF 9216 | MASK 18432 (128 q-rows)
// ---------------------------------------------------------------------------
#define RSTRIDE 144
#define AOFF_QH 0
#define AOFF_QL 18432
#define ASTAGE0 36864
#define AOFF_KH 0
#define AOFF_KL 9216
#define AOFF_VF 18432
#define AOFF_MS 27648
#define ASTAGE_SZ 46080
#define ATTN_SMEM_TOTAL (ASTAGE0 + 3 * ASTAGE_SZ)   // 175104

__global__ __launch_bounds__(256, 1) void attn_mma(
    const __nv_bfloat16* __restrict__ Qh, const __nv_bfloat16* __restrict__ Ql,
    const __nv_bfloat16* __restrict__ Kh, const __nv_bfloat16* __restrict__ Kl,
    const __half* __restrict__ Vf,
    const __nv_bfloat16* __restrict__ maskb,
    __nv_bfloat16* __restrict__ zhi, __nv_bfloat16* __restrict__ zlo)
{
    extern __shared__ char smem[];
    uint32_t sb = smem_u32(smem);
    int tid = threadIdx.x, wid = tid >> 5, lane = tid & 31;
    int b = blockIdx.z, h = blockIdx.y, q0 = blockIdx.x * 128;

    size_t headoff = (size_t)(b * H_ + h) * L_ * DH_;
    const __nv_bfloat16* gQh = Qh + headoff + (size_t)q0 * DH_;
    const __nv_bfloat16* gQl = Ql + headoff + (size_t)q0 * DH_;
    const __nv_bfloat16* gKh = Kh + headoff;
    const __nv_bfloat16* gKl = Kl + headoff;
    const __half* gVf = Vf + headoff;                 // [l][64] fp16
    const __nv_bfloat16* gMk = maskb + ((size_t)b * L_ + q0) * L_;

    auto load_stage = [&](int j) {
        uint32_t stg = sb + ASTAGE0 + (j % 3) * ASTAGE_SZ;
        int k0 = j * 64;
#pragma unroll
        for (int t = 0; t < 4; t++) {       // K hi+lo: 1024 chunks (64 rows each)
            int u = tid + 256 * t;
            int isLo = u >> 9;
            int idx = u & 511;
            int row = idx >> 3, c8 = idx & 7;
            const __nv_bfloat16* sk = (isLo ? gKl : gKh) + (size_t)(k0 + row) * DH_ + c8 * 8;
            cpasync16(stg + (isLo ? AOFF_KL : AOFF_KH) + row * RSTRIDE + c8 * 16, sk);
        }
#pragma unroll
        for (int t = 0; t < 2; t++) {       // V fp16: 512 chunks (64 rows)
            int u = tid + 256 * t;
            int row = u >> 3, c8 = u & 7;
            cpasync16(stg + AOFF_VF + row * RSTRIDE + c8 * 16,
                      gVf + (size_t)(k0 + row) * DH_ + c8 * 8);
        }
#pragma unroll
        for (int t = 0; t < 4; t++) {       // mask: 1024 chunks = 128 q-rows
            int u = tid + 256 * t;
            int row = u >> 3, c8 = u & 7;
            cpasync16(stg + AOFF_MS + row * RSTRIDE + c8 * 16,
                      gMk + (size_t)row * L_ + k0 + c8 * 8);
        }
    };

    // prologue: group0 = Q + stage 0, group1 = stage 1
    {
#pragma unroll
        for (int t = 0; t < 8; t++) {
            int u = tid + 256 * t;
            int isLo = u >> 10;
            int idx = u & 1023;
            int row = idx >> 3, c8 = idx & 7;
            const __nv_bfloat16* sq = (isLo ? gQl : gQh) + (size_t)row * DH_ + c8 * 8;
            cpasync16(sb + (isLo ? AOFF_QL : AOFF_QH) + row * RSTRIDE + c8 * 16, sq);
        }
        load_stage(0);
        CP_COMMIT();
        load_stage(1);
        CP_COMMIT();
    }

    int r0 = lane >> 2, quad = lane & 3;
    uint32_t a_base = (wid * 16 + (lane & 15)) * RSTRIDE + (lane >> 4) * 16;
    uint32_t b_base = ((lane & 7) + ((lane >> 4) << 3)) * RSTRIDE + ((lane >> 3) & 1) * 16;
    int vgrp = lane >> 3;
    uint32_t v_base = ((lane & 7) + (vgrp & 1) * 8) * RSTRIDE + (vgrp >> 1) * 16;

    float o[8][4];
#pragma unroll
    for (int i = 0; i < 8; i++)
#pragma unroll
        for (int j = 0; j < 4; j++) o[i][j] = 0.0f;
    float mpr0 = -INFINITY, mpr1 = -INFINITY;
    float Lm0 = 0.f, Lm1 = 0.f;
    uint32_t qfh[4][4], qfl[4][4];

    for (int j = 0; j < 32; j++) {
        if (j + 2 < 32)      { load_stage(j + 2); CP_COMMIT(); CP_WAIT(2); }
        else if (j + 1 < 32) { CP_WAIT(1); }
        else                 { CP_WAIT(0); }
        __syncthreads();

        if (j == 0) {
#pragma unroll
            for (int ks = 0; ks < 4; ks++) {
                ldsm_x4(qfh[ks], sb + AOFF_QH + a_base + ks * 32);
                ldsm_x4(qfl[ks], sb + AOFF_QL + a_base + ks * 32);
            }
        }
        uint32_t stg = sb + ASTAGE0 + (j % 3) * ASTAGE_SZ;

        // ---- S = Q K^T (3-way bf16 split) ----
        float s[8][4];
#pragma unroll
        for (int i = 0; i < 8; i++)
#pragma unroll
            for (int e = 0; e < 4; e++) s[i][e] = 0.0f;
#pragma unroll
        for (int ks = 0; ks < 4; ks++) {
            uint32_t kh[4][4], kl[4][4];
#pragma unroll
            for (int np = 0; np < 4; np++) {
                uint32_t ad = stg + np * (16 * RSTRIDE) + ks * 32 + b_base;
                ldsm_x4(kh[np], ad + AOFF_KH);
                ldsm_x4(kl[np], ad + AOFF_KL);
            }
#pragma unroll
            for (int nf = 0; nf < 8; nf++) {
                mma_bf16(s[nf], qfh[ks], &kh[nf >> 1][(nf & 1) * 2]);
                mma_bf16(s[nf], qfl[ks], &kh[nf >> 1][(nf & 1) * 2]);
                mma_bf16(s[nf], qfh[ks], &kl[nf >> 1][(nf & 1) * 2]);
            }
        }

        // ---- online softmax (masked-sum only) ----
        float mx0 = -INFINITY, mx1 = -INFINITY;
#pragma unroll
        for (int nf = 0; nf < 8; nf++) {
            mx0 = fmaxf(mx0, fmaxf(s[nf][0], s[nf][1]));
            mx1 = fmaxf(mx1, fmaxf(s[nf][2], s[nf][3]));
        }
        mx0 = fmaxf(mx0, __shfl_xor_sync(0xffffffffu, mx0, 1));
        mx0 = fmaxf(mx0, __shfl_xor_sync(0xffffffffu, mx0, 2));
        mx1 = fmaxf(mx1, __shfl_xor_sync(0xffffffffu, mx1, 1));
        mx1 = fmaxf(mx1, __shfl_xor_sync(0xffffffffu, mx1, 2));
        float mn0 = fmaxf(mpr0, mx0), mn1 = fmaxf(mpr1, mx1);
        float cf0 = __expf(mpr0 - mn0), cf1 = __expf(mpr1 - mn1);
        mpr0 = mn0; mpr1 = mn1;

        float ls0 = 0.f, ls1 = 0.f;
        uint32_t mrow = (wid * 16 + r0) * RSTRIDE + quad * 4;
#pragma unroll
        for (int nf = 0; nf < 8; nf++) {
            float p0 = __expf(s[nf][0] - mn0);
            float p1 = __expf(s[nf][1] - mn0);
            float p2 = __expf(s[nf][2] - mn1);
            float p3 = __expf(s[nf][3] - mn1);
            uint32_t m01 = lds32(stg + AOFF_MS + mrow + nf * 16);
            uint32_t m23 = lds32(stg + AOFF_MS + mrow + 8 * RSTRIDE + nf * 16);
            p0 *= bf_lo(m01); p1 *= bf_hi(m01);
            p2 *= bf_lo(m23); p3 *= bf_hi(m23);
            ls0 += p0 + p1;
            ls1 += p2 + p3;
            s[nf][0] = p0; s[nf][1] = p1; s[nf][2] = p2; s[nf][3] = p3;
        }
        ls0 += __shfl_xor_sync(0xffffffffu, ls0, 1); ls0 += __shfl_xor_sync(0xffffffffu, ls0, 2);
        ls1 += __shfl_xor_sync(0xffffffffu, ls1, 1); ls1 += __shfl_xor_sync(0xffffffffu, ls1, 2);
        Lm0 = Lm0 * cf0 + ls0; Lm1 = Lm1 * cf1 + ls1;

#pragma unroll
        for (int nf = 0; nf < 8; nf++) {
            o[nf][0] *= cf0; o[nf][1] *= cf0;
            o[nf][2] *= cf1; o[nf][3] *= cf1;
        }

        // ---- O += P V, single-pass fp16, V frags via ldmatrix.trans ----
#pragma unroll
        for (int ks = 0; ks < 4; ks++) {
            uint32_t pf[4];
            pf[0] = hpack(s[2 * ks][0], s[2 * ks][1]);
            pf[1] = hpack(s[2 * ks][2], s[2 * ks][3]);
            pf[2] = hpack(s[2 * ks + 1][0], s[2 * ks + 1][1]);
            pf[3] = hpack(s[2 * ks + 1][2], s[2 * ks + 1][3]);
            uint32_t vv[4][4];
#pragma unroll
            for (int np = 0; np < 4; np++) {
                uint32_t ad = stg + ks * (16 * RSTRIDE) + np * 32 + v_base;
                ldsm_x4_t(vv[np], ad + AOFF_VF);
            }
#pragma unroll
            for (int nd = 0; nd < 8; nd++)
                mma_f16(o[nd], pf, &vv[nd >> 1][(nd & 1) * 2]);
        }
        __syncthreads();
    }

    // ---- epilogue: z = O / Lm as split bf16 ----
    float inv0 = 1.0f / (Lm0 + 1e-30f);
    float inv1 = 1.0f / (Lm1 + 1e-30f);
    int row0 = q0 + wid * 16 + r0;
    int colb = h * DH_ + quad * 2;
#pragma unroll
    for (int nd = 0; nd < 8; nd++) {
        int col = colb + nd * 8;
        float z0 = o[nd][0] * inv0, z1 = o[nd][1] * inv0;
        float z2 = o[nd][2] * inv1, z3 = o[nd][3] * inv1;
        uint32_t h01 = bfpack(z0, z1);
        uint32_t h23 = bfpack(z2, z3);
        uint32_t l01 = bfpack(z0 - bf_lo(h01), z1 - bf_hi(h01));
        uint32_t l23 = bfpack(z2 - bf_lo(h23), z3 - bf_hi(h23));
        size_t i0 = ((size_t)b * L_ + row0) * DIM_ + col;
        size_t i1 = ((size_t)b * L_ + row0 + 8) * DIM_ + col;
        *(uint32_t*)(zhi + i0) = h01;
        *(uint32_t*)(zlo + i0) = l01;
        *(uint32_t*)(zhi + i1) = h23;
        *(uint32_t*)(zlo + i1) = l23;
    }
}

// ---------------------------------------------------------------------------
extern "C" void kernel_launch(void* const* d_in, const int* in_sizes, int n_in,
                              void* d_out, int out_size)
{
    const float* x    = (const float*)d_in[0];
    const float* mask = (const float*)d_in[1];
    const float* Wqkv = (const float*)d_in[2];
    const float* Wout = (const float*)d_in[3];
    const float* bout = (const float*)d_in[4];
    float* out = (float*)d_out;

    __nv_bfloat16 *ahi, *alo, *wqh, *wql, *woh, *wol;
    __nv_bfloat16 *qh, *ql, *kh, *kl, *mb;
    __half* vf;
    cudaGetSymbolAddress((void**)&ahi, g_ahi);
    cudaGetSymbolAddress((void**)&alo, g_alo);
    cudaGetSymbolAddress((void**)&wqh, g_wqt_hi);
    cudaGetSymbolAddress((void**)&wql, g_wqt_lo);
    cudaGetSymbolAddress((void**)&woh, g_wot_hi);
    cudaGetSymbolAddress((void**)&wol, g_wot_lo);
    cudaGetSymbolAddress((void**)&qh, g_qh);
    cudaGetSymbolAddress((void**)&ql, g_ql);
    cudaGetSymbolAddress((void**)&kh, g_kh);
    cudaGetSymbolAddress((void**)&kl, g_kl);
    cudaGetSymbolAddress((void**)&vf, g_vf);
    cudaGetSymbolAddress((void**)&mb, g_maskb);

    cudaFuncSetAttribute(mm_hmma<true>,  cudaFuncAttributeMaxDynamicSharedMemorySize, GEMM_SMEM);
    cudaFuncSetAttribute(mm_hmma<false>, cudaFuncAttributeMaxDynamicSharedMemorySize, GEMM_SMEM);
    cudaFuncSetAttribute(attn_mma, cudaFuncAttributeMaxDynamicSharedMemorySize, ATTN_SMEM_TOTAL);

    // prep: split x, transpose+split weights, mask -> bf16
    split_fp32<<<(B_ * L_ * DIM_ / 4 + 255) / 256, 256>>>(x, ahi, alo, B_ * L_ * DIM_ / 4);
    transpose_split<<<dim3(N3_ / 32, DIM_ / 32), dim3(32, 8)>>>(Wqkv, wqh, wql, DIM_, N3_);
    transpose_split<<<dim3(DIM_ / 32, DIM_ / 32), dim3(32, 8)>>>(Wout, woh, wol, DIM_, DIM_);
    mask_bf16<<<(B_ * L_ * L_ / 4 + 255) / 256, 256>>>(mask, mb, B_ * L_ * L_ / 4);

    // QKV projection -> q/k split bf16, v fp16, [b,h,l,64]
    mm_hmma<true><<<dim3(N3_ / 128, (B_ * L_) / 128), 256, GEMM_SMEM>>>(
        ahi, alo, wqh, wql, nullptr, nullptr,
        qh, ql, kh, kl, vf, B_ * L_, N3_, DIM_);

    // flash attention -> split z into ahi/alo
    attn_mma<<<dim3(L_ / 128, H_, B_), 256, ATTN_SMEM_TOTAL>>>(
        qh, ql, kh, kl, vf, mb, ahi, alo);

    // output projection (+bias)
    mm_hmma<false><<<dim3(DIM_ / 128, (B_ * L_) / 128), 256, GEMM_SMEM>>>(
        ahi, alo, woh, wol, bout, out,
        nullptr, nullptr, nullptr, nullptr, nullptr,
        B_ * L_, DIM_, DIM_);
}

// round 13
// speedup vs baseline: 1.4370x; 1.4370x over previous
#include <cuda_runtime.h>
#include <cuda_bf16.h>
#include <cuda_fp16.h>
#include <cstdint>
#include <math.h>

#define B_    2
#define L_    2048
#define DIM_  1024
#define H_    16
#define DH_   64
#define N3_   3072
#define SCALE_ 0.125f

// ---------------- device scratch ----------------
__device__ __half g_xhi[B_ * L_ * DIM_];   // x split hi (later z split hi)
__device__ __half g_xlo[B_ * L_ * DIM_];   // x split lo (later z split lo)
__device__ __half g_wqt[N3_ * DIM_];       // Wqkv^T single fp16
__device__ __half g_wot[DIM_ * DIM_];      // Wout^T single fp16
// attention operands [b,h,l,64] (written by QKV GEMM epilogue)
__device__ __half g_qh[B_ * H_ * L_ * DH_];   // Q hi (scaled by 0.125)
__device__ __half g_ql[B_ * H_ * L_ * DH_];   // Q lo
__device__ __half g_kf[B_ * H_ * L_ * DH_];   // K single fp16
__device__ __half g_vf[B_ * H_ * L_ * DH_];   // V single fp16
__device__ __nv_bfloat16 g_maskb[B_ * L_ * L_];

// ---------------- helpers ----------------
__device__ __forceinline__ uint32_t smem_u32(const void* p) {
    uint32_t a;
    asm("{ .reg .u64 t; cvta.to.shared.u64 t, %1; cvt.u32.u64 %0, t; }" : "=r"(a) : "l"(p));
    return a;
}
__device__ __forceinline__ void cpasync16(uint32_t s, const void* g) {
    asm volatile("cp.async.cg.shared.global [%0], [%1], 16;" :: "r"(s), "l"(g));
}
#define CP_COMMIT() asm volatile("cp.async.commit_group;")
#define CP_WAIT(n)  asm volatile("cp.async.wait_group %0;" :: "n"(n))

__device__ __forceinline__ void ldsm_x4(uint32_t r[4], uint32_t addr) {
    asm volatile("ldmatrix.sync.aligned.m8n8.x4.shared.b16 {%0,%1,%2,%3}, [%4];"
                 : "=r"(r[0]), "=r"(r[1]), "=r"(r[2]), "=r"(r[3]) : "r"(addr));
}
__device__ __forceinline__ void ldsm_x4_t(uint32_t r[4], uint32_t addr) {
    asm volatile("ldmatrix.sync.aligned.m8n8.x4.trans.shared.b16 {%0,%1,%2,%3}, [%4];"
                 : "=r"(r[0]), "=r"(r[1]), "=r"(r[2]), "=r"(r[3]) : "r"(addr));
}
__device__ __forceinline__ void mma_f16(float c[4], const uint32_t a[4], const uint32_t b[2]) {
    asm volatile(
        "mma.sync.aligned.m16n8k16.row.col.f32.f16.f16.f32 "
        "{%0,%1,%2,%3}, {%4,%5,%6,%7}, {%8,%9}, {%0,%1,%2,%3};"
        : "+f"(c[0]), "+f"(c[1]), "+f"(c[2]), "+f"(c[3])
        : "r"(a[0]), "r"(a[1]), "r"(a[2]), "r"(a[3]), "r"(b[0]), "r"(b[1]));
}
__device__ __forceinline__ uint32_t hpack(float lo, float hi) {
    uint32_t r;
    asm("cvt.rn.f16x2.f32 %0, %1, %2;" : "=r"(r) : "f"(hi), "f"(lo));
    return r;
}
__device__ __forceinline__ float hf_lo(uint32_t u) {
    return __half2float(__ushort_as_half((unsigned short)(u & 0xffffu)));
}
__device__ __forceinline__ float hf_hi(uint32_t u) {
    return __half2float(__ushort_as_half((unsigned short)(u >> 16)));
}
__device__ __forceinline__ float bf_lo(uint32_t u) { return __uint_as_float(u << 16); }
__device__ __forceinline__ float bf_hi(uint32_t u) { return __uint_as_float(u & 0xffff0000u); }
__device__ __forceinline__ uint32_t lds32(uint32_t a) {
    uint32_t v;
    asm volatile("ld.shared.b32 %0, [%1];" : "=r"(v) : "r"(a));
    return v;
}

// ---------------------------------------------------------------------------
// fp32 -> (hi, lo) fp16 split (hi+lo exact to ~2^-22)
// ---------------------------------------------------------------------------
__global__ __launch_bounds__(256) void split_fp16(
    const float* __restrict__ in, __half* __restrict__ hi,
    __half* __restrict__ lo, int n4)
{
    int i = blockIdx.x * blockDim.x + threadIdx.x;
    if (i >= n4) return;
    float4 v = ((const float4*)in)[i];
    float vv[4] = {v.x, v.y, v.z, v.w};
    __half h[4], l[4];
#pragma unroll
    for (int k = 0; k < 4; k++) {
        h[k] = __float2half(vv[k]);
        l[k] = __float2half(vv[k] - __half2float(h[k]));
    }
    ((uint2*)hi)[i] = *(uint2*)h;
    ((uint2*)lo)[i] = *(uint2*)l;
}

// fp32 mask -> bf16 (0/1 exact)
__global__ __launch_bounds__(256) void mask_bf16(
    const float* __restrict__ in, __nv_bfloat16* __restrict__ o, int n4)
{
    int i = blockIdx.x * blockDim.x + threadIdx.x;
    if (i >= n4) return;
    float4 v = ((const float4*)in)[i];
    __nv_bfloat16 h[4] = {__float2bfloat16(v.x), __float2bfloat16(v.y),
                          __float2bfloat16(v.z), __float2bfloat16(v.w)};
    ((uint2*)o)[i] = *(uint2*)h;
}

// ---------------------------------------------------------------------------
// fp32 [R,C] -> transposed single fp16 [C,R] (weights; B-side rounding)
// ---------------------------------------------------------------------------
__global__ __launch_bounds__(256) void transpose_f16(
    const float* __restrict__ in, __half* __restrict__ o, int R, int C)
{
    __shared__ float t[32][33];
    int cb = blockIdx.x * 32, rb = blockIdx.y * 32;
    int tx = threadIdx.x, ty = threadIdx.y;
#pragma unroll
    for (int i = 0; i < 4; i++)
        t[ty + 8 * i][tx] = in[(size_t)(rb + ty + 8 * i) * C + cb + tx];
    __syncthreads();
#pragma unroll
    for (int i = 0; i < 4; i++) {
        size_t oo = (size_t)(cb + ty + 8 * i) * R + rb + tx;
        o[oo] = __float2half(t[tx][ty + 8 * i]);
    }
}

// ---------------------------------------------------------------------------
// HMMA fp16 2-pass GEMM: C = (Ahi+Alo)[M,K] @ B[N,K]^T, B single fp16.
// QKVOUT=true: q as fp16 hi/lo (scaled 2^-3), k/v single fp16, [b,h,l,64].
// QKVOUT=false: fp32 C + bias.
// 2-stage cp.async pipeline. smem arrays per stage: AH | AL | B.
// ---------------------------------------------------------------------------
#define MMPAD 40
#define STG_BYTES (3 * 128 * MMPAD * 2)   // 30720 per stage
#define OFF_AH 0
#define OFF_AL (128 * MMPAD * 2)
#define OFF_B  (2 * 128 * MMPAD * 2)
#define GEMM_SMEM (2 * STG_BYTES)         // 61440

template <bool QKVOUT>
__global__ __launch_bounds__(256, 1) void mm_hmma(
    const __half* __restrict__ Ahi, const __half* __restrict__ Alo,
    const __half* __restrict__ Bm,
    const float* __restrict__ bias, float* __restrict__ C,
    __half* __restrict__ qh, __half* __restrict__ ql,
    __half* __restrict__ kf, __half* __restrict__ vf,
    int M, int N, int K)
{
    extern __shared__ char smem[];
    uint32_t sb = smem_u32(smem);
    int tid = threadIdx.x, wid = tid >> 5, lane = tid & 31;
    int m0 = blockIdx.y * 128, n0 = blockIdx.x * 128;
    int wm = wid & 3, wn = wid >> 2;

    const __half* gAh = Ahi + (size_t)m0 * K;
    const __half* gAl = Alo + (size_t)m0 * K;
    const __half* gB  = Bm + (size_t)n0 * K;

    auto load_chunk = [&](int c) {
        uint32_t stg = sb + (c & 1) * STG_BYTES;
        int kc = c * 32;
        // 3 arrays x 512 16B-chunks = 1536; 6 per thread
#pragma unroll
        for (int t = 0; t < 6; t++) {
            int u = tid + 256 * t;
            int arr = u >> 9;          // 0=AH 1=AL 2=B
            int idx = u & 511;
            int row = idx >> 2, c8 = (idx & 3) * 8;
            const __half* src = (arr == 0 ? gAh : arr == 1 ? gAl : gB)
                                + (size_t)row * K + kc + c8;
            uint32_t dst = stg + arr * (128 * MMPAD * 2) + (row * MMPAD + c8) * 2;
            cpasync16(dst, src);
        }
    };

    float acc[2][8][4];
#pragma unroll
    for (int mi = 0; mi < 2; mi++)
#pragma unroll
        for (int ni = 0; ni < 8; ni++)
#pragma unroll
            for (int j = 0; j < 4; j++) acc[mi][ni][j] = 0.0f;

    const int NCH = K >> 5;
    uint32_t a_row = wm * 32 + (lane & 15);
    uint32_t a_k8 = (lane >> 4) * 8;
    uint32_t b_row = wn * 64 + (lane & 7) + ((lane >> 4) << 3);
    uint32_t b_k8 = ((lane >> 3) & 1) * 8;

    load_chunk(0); CP_COMMIT();

    for (int c = 0; c < NCH; c++) {
        if (c + 1 < NCH) { load_chunk(c + 1); CP_COMMIT(); CP_WAIT(1); }
        else             { CP_WAIT(0); }
        __syncthreads();

        uint32_t stg = sb + (c & 1) * STG_BYTES;
#pragma unroll
        for (int ks = 0; ks < 2; ks++) {
            uint32_t ah[2][4], al[2][4];
#pragma unroll
            for (int mi = 0; mi < 2; mi++) {
                uint32_t ao = ((a_row + mi * 16) * MMPAD + ks * 16 + a_k8) * 2;
                ldsm_x4(ah[mi], stg + OFF_AH + ao);
                ldsm_x4(al[mi], stg + OFF_AL + ao);
            }
#pragma unroll
            for (int half = 0; half < 2; half++) {
                uint32_t bf[2][4];
#pragma unroll
                for (int nb = 0; nb < 2; nb++) {
                    uint32_t bo = ((b_row + (half * 2 + nb) * 16) * MMPAD + ks * 16 + b_k8) * 2;
                    ldsm_x4(bf[nb], stg + OFF_B + bo);
                }
#pragma unroll
                for (int mi = 0; mi < 2; mi++)
#pragma unroll
                    for (int nq = 0; nq < 4; nq++)
                        mma_f16(acc[mi][half * 4 + nq], ah[mi], &bf[nq >> 1][(nq & 1) * 2]);
#pragma unroll
                for (int mi = 0; mi < 2; mi++)
#pragma unroll
                    for (int nq = 0; nq < 4; nq++)
                        mma_f16(acc[mi][half * 4 + nq], al[mi], &bf[nq >> 1][(nq & 1) * 2]);
            }
        }
        __syncthreads();
    }

    if (QKVOUT) {
        int gcol0 = n0 + wn * 64;
        int which = gcol0 >> 10;          // 0=q, 1=k, 2=v
        int hh = (gcol0 & 1023) >> 6;
        int rbase = m0 + wm * 32 + (lane >> 2);
        int d0 = (lane & 3) * 2;
        if (which == 0) {
            // Q: fp16 hi/lo, scaled by 2^-3 (exact)
#pragma unroll
            for (int mi = 0; mi < 2; mi++) {
#pragma unroll
                for (int ni = 0; ni < 8; ni++) {
                    int d = d0 + ni * 8;
#pragma unroll
                    for (int half = 0; half < 2; half++) {
                        int rr = rbase + mi * 16 + half * 8;
                        int bb = rr >> 11, ll = rr & 2047;
                        float v0 = acc[mi][ni][half * 2 + 0] * SCALE_;
                        float v1 = acc[mi][ni][half * 2 + 1] * SCALE_;
                        uint32_t hp = hpack(v0, v1);
                        uint32_t lp = hpack(v0 - hf_lo(hp), v1 - hf_hi(hp));
                        size_t o = ((size_t)(bb * H_ + hh) * L_ + ll) * DH_ + d;
                        *(uint32_t*)(qh + o) = hp;
                        *(uint32_t*)(ql + o) = lp;
                    }
                }
            }
        } else {
            __half* dst = (which == 1) ? kf : vf;
#pragma unroll
            for (int mi = 0; mi < 2; mi++) {
#pragma unroll
                for (int ni = 0; ni < 8; ni++) {
                    int d = d0 + ni * 8;
#pragma unroll
                    for (int half = 0; half < 2; half++) {
                        int rr = rbase + mi * 16 + half * 8;
                        int bb = rr >> 11, ll = rr & 2047;
                        uint32_t vp = hpack(acc[mi][ni][half * 2 + 0],
                                            acc[mi][ni][half * 2 + 1]);
                        size_t o = ((size_t)(bb * H_ + hh) * L_ + ll) * DH_ + d;
                        *(uint32_t*)(dst + o) = vp;
                    }
                }
            }
        }
    } else {
        int rbase = m0 + wm * 32 + (lane >> 2);
        int cb0 = n0 + wn * 64 + (lane & 3) * 2;
#pragma unroll
        for (int mi = 0; mi < 2; mi++) {
#pragma unroll
            for (int ni = 0; ni < 8; ni++) {
                int rr = rbase + mi * 16;
                int cc = cb0 + ni * 8;
                float b0 = bias[cc], b1 = bias[cc + 1];
                float2 v0 = {acc[mi][ni][0] + b0, acc[mi][ni][1] + b1};
                float2 v1 = {acc[mi][ni][2] + b0, acc[mi][ni][3] + b1};
                *(float2*)&C[(size_t)rr * N + cc] = v0;
                *(float2*)&C[(size_t)(rr + 8) * N + cc] = v1;
            }
        }
    }
}

// ---------------------------------------------------------------------------
// Tensor-core flash attention, post-softmax mask + renorm.
// Q tile 128 x KV block 64, 8 warps, 2-stage pipeline.
// S = QK^T: Q fp16 hi/lo (2 passes), K single fp16.
// P,V fp16 single-pass. No Zf track.
// Stage layout (bytes): KF 9216 | VF 9216 | MASK 18432 (128 q-rows)
// ---------------------------------------------------------------------------
#define RSTRIDE 144
#define AOFF_QH 0
#define AOFF_QL 18432
#define ASTAGE0 36864
#define AOFF_KF 0
#define AOFF_VF 9216
#define AOFF_MS 18432
#define ASTAGE_SZ 36864
#define ATTN_SMEM_TOTAL (ASTAGE0 + 2 * ASTAGE_SZ)   // 110592

__global__ __launch_bounds__(256, 1) void attn_mma(
    const __half* __restrict__ Qh, const __half* __restrict__ Ql,
    const __half* __restrict__ Kf, const __half* __restrict__ Vf,
    const __nv_bfloat16* __restrict__ maskb,
    __half* __restrict__ zhi, __half* __restrict__ zlo)
{
    extern __shared__ char smem[];
    uint32_t sb = smem_u32(smem);
    int tid = threadIdx.x, wid = tid >> 5, lane = tid & 31;
    int b = blockIdx.z, h = blockIdx.y, q0 = blockIdx.x * 128;

    size_t headoff = (size_t)(b * H_ + h) * L_ * DH_;
    const __half* gQh = Qh + headoff + (size_t)q0 * DH_;
    const __half* gQl = Ql + headoff + (size_t)q0 * DH_;
    const __half* gKf = Kf + headoff;
    const __half* gVf = Vf + headoff;
    const __nv_bfloat16* gMk = maskb + ((size_t)b * L_ + q0) * L_;

    auto load_stage = [&](int j) {
        uint32_t stg = sb + ASTAGE0 + (j & 1) * ASTAGE_SZ;
        int k0 = j * 64;
#pragma unroll
        for (int t = 0; t < 2; t++) {       // K fp16: 512 chunks (64 rows)
            int u = tid + 256 * t;
            int row = u >> 3, c8 = u & 7;
            cpasync16(stg + AOFF_KF + row * RSTRIDE + c8 * 16,
                      gKf + (size_t)(k0 + row) * DH_ + c8 * 8);
        }
#pragma unroll
        for (int t = 0; t < 2; t++) {       // V fp16: 512 chunks (64 rows)
            int u = tid + 256 * t;
            int row = u >> 3, c8 = u & 7;
            cpasync16(stg + AOFF_VF + row * RSTRIDE + c8 * 16,
                      gVf + (size_t)(k0 + row) * DH_ + c8 * 8);
        }
#pragma unroll
        for (int t = 0; t < 4; t++) {       // mask: 1024 chunks = 128 q-rows
            int u = tid + 256 * t;
            int row = u >> 3, c8 = u & 7;
            cpasync16(stg + AOFF_MS + row * RSTRIDE + c8 * 16,
                      gMk + (size_t)row * L_ + k0 + c8 * 8);
        }
    };

    {
#pragma unroll
        for (int t = 0; t < 8; t++) {       // Q hi+lo: 2048 chunks (128 rows each)
            int u = tid + 256 * t;
            int isLo = u >> 10;
            int idx = u & 1023;
            int row = idx >> 3, c8 = idx & 7;
            const __half* sq = (isLo ? gQl : gQh) + (size_t)row * DH_ + c8 * 8;
            cpasync16(sb + (isLo ? AOFF_QL : AOFF_QH) + row * RSTRIDE + c8 * 16, sq);
        }
        load_stage(0);
        CP_COMMIT();
    }

    int r0 = lane >> 2, quad = lane & 3;
    uint32_t a_base = (wid * 16 + (lane & 15)) * RSTRIDE + (lane >> 4) * 16;
    uint32_t b_base = ((lane & 7) + ((lane >> 4) << 3)) * RSTRIDE + ((lane >> 3) & 1) * 16;
    int vgrp = lane >> 3;
    uint32_t v_base = ((lane & 7) + (vgrp & 1) * 8) * RSTRIDE + (vgrp >> 1) * 16;

    float o[8][4];
#pragma unroll
    for (int i = 0; i < 8; i++)
#pragma unroll
        for (int j = 0; j < 4; j++) o[i][j] = 0.0f;
    float mpr0 = -INFINITY, mpr1 = -INFINITY;
    float Lm0 = 0.f, Lm1 = 0.f;
    uint32_t qfh[4][4], qfl[4][4];

    for (int j = 0; j < 32; j++) {
        if (j + 1 < 32) { load_stage(j + 1); CP_COMMIT(); CP_WAIT(1); }
        else            { CP_WAIT(0); }
        __syncthreads();

        if (j == 0) {
#pragma unroll
            for (int ks = 0; ks < 4; ks++) {
                ldsm_x4(qfh[ks], sb + AOFF_QH + a_base + ks * 32);
                ldsm_x4(qfl[ks], sb + AOFF_QL + a_base + ks * 32);
            }
        }
        uint32_t stg = sb + ASTAGE0 + (j & 1) * ASTAGE_SZ;

        // ---- S = Q K^T (2-pass: Qh*K + Ql*K) ----
        float s[8][4];
#pragma unroll
        for (int i = 0; i < 8; i++)
#pragma unroll
            for (int e = 0; e < 4; e++) s[i][e] = 0.0f;
#pragma unroll
        for (int ks = 0; ks < 4; ks++) {
            uint32_t kk[4][4];
#pragma unroll
            for (int np = 0; np < 4; np++) {
                uint32_t ad = stg + np * (16 * RSTRIDE) + ks * 32 + b_base;
                ldsm_x4(kk[np], ad + AOFF_KF);
            }
#pragma unroll
            for (int nf = 0; nf < 8; nf++) {
                mma_f16(s[nf], qfh[ks], &kk[nf >> 1][(nf & 1) * 2]);
                mma_f16(s[nf], qfl[ks], &kk[nf >> 1][(nf & 1) * 2]);
            }
        }

        // ---- online softmax (masked-sum only) ----
        float mx0 = -INFINITY, mx1 = -INFINITY;
#pragma unroll
        for (int nf = 0; nf < 8; nf++) {
            mx0 = fmaxf(mx0, fmaxf(s[nf][0], s[nf][1]));
            mx1 = fmaxf(mx1, fmaxf(s[nf][2], s[nf][3]));
        }
        mx0 = fmaxf(mx0, __shfl_xor_sync(0xffffffffu, mx0, 1));
        mx0 = fmaxf(mx0, __shfl_xor_sync(0xffffffffu, mx0, 2));
        mx1 = fmaxf(mx1, __shfl_xor_sync(0xffffffffu, mx1, 1));
        mx1 = fmaxf(mx1, __shfl_xor_sync(0xffffffffu, mx1, 2));
        float mn0 = fmaxf(mpr0, mx0), mn1 = fmaxf(mpr1, mx1);
        float cf0 = __expf(mpr0 - mn0), cf1 = __expf(mpr1 - mn1);
        mpr0 = mn0; mpr1 = mn1;

        float ls0 = 0.f, ls1 = 0.f;
        uint32_t mrow = (wid * 16 + r0) * RSTRIDE + quad * 4;
#pragma unroll
        for (int nf = 0; nf < 8; nf++) {
            float p0 = __expf(s[nf][0] - mn0);
            float p1 = __expf(s[nf][1] - mn0);
            float p2 = __expf(s[nf][2] - mn1);
            float p3 = __expf(s[nf][3] - mn1);
            uint32_t m01 = lds32(stg + AOFF_MS + mrow + nf * 16);
            uint32_t m23 = lds32(stg + AOFF_MS + mrow + 8 * RSTRIDE + nf * 16);
            p0 *= bf_lo(m01); p1 *= bf_hi(m01);
            p2 *= bf_lo(m23); p3 *= bf_hi(m23);
            ls0 += p0 + p1;
            ls1 += p2 + p3;
            s[nf][0] = p0; s[nf][1] = p1; s[nf][2] = p2; s[nf][3] = p3;
        }
        ls0 += __shfl_xor_sync(0xffffffffu, ls0, 1); ls0 += __shfl_xor_sync(0xffffffffu, ls0, 2);
        ls1 += __shfl_xor_sync(0xffffffffu, ls1, 1); ls1 += __shfl_xor_sync(0xffffffffu, ls1, 2);
        Lm0 = Lm0 * cf0 + ls0; Lm1 = Lm1 * cf1 + ls1;

#pragma unroll
        for (int nf = 0; nf < 8; nf++) {
            o[nf][0] *= cf0; o[nf][1] *= cf0;
            o[nf][2] *= cf1; o[nf][3] *= cf1;
        }

        // ---- O += P V, single-pass fp16, V frags via ldmatrix.trans ----
#pragma unroll
        for (int ks = 0; ks < 4; ks++) {
            uint32_t pf[4];
            pf[0] = hpack(s[2 * ks][0], s[2 * ks][1]);
            pf[1] = hpack(s[2 * ks][2], s[2 * ks][3]);
            pf[2] = hpack(s[2 * ks + 1][0], s[2 * ks + 1][1]);
            pf[3] = hpack(s[2 * ks + 1][2], s[2 * ks + 1][3]);
            uint32_t vv[4][4];
#pragma unroll
            for (int np = 0; np < 4; np++) {
                uint32_t ad = stg + ks * (16 * RSTRIDE) + np * 32 + v_base;
                ldsm_x4_t(vv[np], ad + AOFF_VF);
            }
#pragma unroll
            for (int nd = 0; nd < 8; nd++)
                mma_f16(o[nd], pf, &vv[nd >> 1][(nd & 1) * 2]);
        }
        __syncthreads();
    }

    // ---- epilogue: z = O / Lm as split fp16 ----
    float inv0 = 1.0f / (Lm0 + 1e-30f);
    float inv1 = 1.0f / (Lm1 + 1e-30f);
    int row0 = q0 + wid * 16 + r0;
    int colb = h * DH_ + quad * 2;
#pragma unroll
    for (int nd = 0; nd < 8; nd++) {
        int col = colb + nd * 8;
        float z0 = o[nd][0] * inv0, z1 = o[nd][1] * inv0;
        float z2 = o[nd][2] * inv1, z3 = o[nd][3] * inv1;
        uint32_t h01 = hpack(z0, z1);
        uint32_t h23 = hpack(z2, z3);
        uint32_t l01 = hpack(z0 - hf_lo(h01), z1 - hf_hi(h01));
        uint32_t l23 = hpack(z2 - hf_lo(h23), z3 - hf_hi(h23));
        size_t i0 = ((size_t)b * L_ + row0) * DIM_ + col;
        size_t i1 = ((size_t)b * L_ + row0 + 8) * DIM_ + col;
        *(uint32_t*)(zhi + i0) = h01;
        *(uint32_t*)(zlo + i0) = l01;
        *(uint32_t*)(zhi + i1) = h23;
        *(uint32_t*)(zlo + i1) = l23;
    }
}

// ---------------------------------------------------------------------------
extern "C" void kernel_launch(void* const* d_in, const int* in_sizes, int n_in,
                              void* d_out, int out_size)
{
    const float* x    = (const float*)d_in[0];
    const float* mask = (const float*)d_in[1];
    const float* Wqkv = (const float*)d_in[2];
    const float* Wout = (const float*)d_in[3];
    const float* bout = (const float*)d_in[4];
    float* out = (float*)d_out;

    __half *xhi, *xlo, *wqt, *wot, *qh, *ql, *kf, *vf;
    __nv_bfloat16* mb;
    cudaGetSymbolAddress((void**)&xhi, g_xhi);
    cudaGetSymbolAddress((void**)&xlo, g_xlo);
    cudaGetSymbolAddress((void**)&wqt, g_wqt);
    cudaGetSymbolAddress((void**)&wot, g_wot);
    cudaGetSymbolAddress((void**)&qh, g_qh);
    cudaGetSymbolAddress((void**)&ql, g_ql);
    cudaGetSymbolAddress((void**)&kf, g_kf);
    cudaGetSymbolAddress((void**)&vf, g_vf);
    cudaGetSymbolAddress((void**)&mb, g_maskb);

    cudaFuncSetAttribute(mm_hmma<true>,  cudaFuncAttributeMaxDynamicSharedMemorySize, GEMM_SMEM);
    cudaFuncSetAttribute(mm_hmma<false>, cudaFuncAttributeMaxDynamicSharedMemorySize, GEMM_SMEM);
    cudaFuncSetAttribute(attn_mma, cudaFuncAttributeMaxDynamicSharedMemorySize, ATTN_SMEM_TOTAL);

    // prep: split x (fp16 hi/lo), transpose weights (single fp16), mask bf16
    split_fp16<<<(B_ * L_ * DIM_ / 4 + 255) / 256, 256>>>(x, xhi, xlo, B_ * L_ * DIM_ / 4);
    transpose_f16<<<dim3(N3_ / 32, DIM_ / 32), dim3(32, 8)>>>(Wqkv, wqt, DIM_, N3_);
    transpose_f16<<<dim3(DIM_ / 32, DIM_ / 32), dim3(32, 8)>>>(Wout, wot, DIM_, DIM_);
    mask_bf16<<<(B_ * L_ * L_ / 4 + 255) / 256, 256>>>(mask, mb, B_ * L_ * L_ / 4);

    // QKV projection -> q fp16 hi/lo (scaled), k/v single fp16, [b,h,l,64]
    mm_hmma<true><<<dim3(N3_ / 128, (B_ * L_) / 128), 256, GEMM_SMEM>>>(
        xhi, xlo, wqt, nullptr, nullptr,
        qh, ql, kf, vf, B_ * L_, N3_, DIM_);

    // flash attention -> split z into xhi/xlo (x no longer needed)
    attn_mma<<<dim3(L_ / 128, H_, B_), 256, ATTN_SMEM_TOTAL>>>(
        qh, ql, kf, vf, mb, xhi, xlo);

    // output projection (+bias)
    mm_hmma<false><<<dim3(DIM_ / 128, (B_ * L_) / 128), 256, GEMM_SMEM>>>(
        xhi, xlo, wot, bout, out,
        nullptr, nullptr, nullptr, nullptr,
        B_ * L_, DIM_, DIM_);
}